// round 9
// baseline (speedup 1.0000x reference)
#include <cuda_runtime.h>

#define HH 256
#define WW 256
#define PP 512
// ALPHA = -5.0f, 1/ALPHA = -0.2f

typedef unsigned long long ull;

__device__ float g_sum[PP];          // zero-init at load; reset by epilogue
__device__ float g_numA[HH];
__device__ float g_denA[HH];
__device__ int   g_ctr = 0;

__device__ __forceinline__ float frsqrt_a(float x) {
    float r; asm("rsqrt.approx.f32 %0, %1;" : "=f"(r) : "f"(x)); return r;
}
__device__ __forceinline__ ull pk2(float lo, float hi) {
    ull r; asm("mov.b64 %0, {%1, %2};" : "=l"(r) : "f"(lo), "f"(hi)); return r;
}
__device__ __forceinline__ void upk2(ull v, float& lo, float& hi) {
    asm("mov.b64 {%0, %1}, %2;" : "=f"(lo), "=f"(hi) : "l"(v));
}
__device__ __forceinline__ ull f2add(ull a, ull b) {
    ull r; asm("add.rn.f32x2 %0, %1, %2;" : "=l"(r) : "l"(a), "l"(b)); return r;
}
__device__ __forceinline__ ull f2mul(ull a, ull b) {
    ull r; asm("mul.rn.f32x2 %0, %1, %2;" : "=l"(r) : "l"(a), "l"(b)); return r;
}
__device__ __forceinline__ ull f2fma(ull a, ull b, ull c) {
    ull r; asm("fma.rn.f32x2 %0, %1, %2, %3;" : "=l"(r) : "l"(a), "l"(b), "l"(c)); return r;
}

// ---------------------------------------------------------------------------
// 256 blocks x 1024 threads, 2 resident blocks/SM (launch_bounds(1024,2)):
// all blocks co-resident, critical SMs run 16 warps/SMSP. One block = one
// heat-map row. Phase A: 4 point-groups x 256 pixels. Phase B: 512 points x
// 2 pixel-halves, f32x2 over pixel pairs, packed Newton reciprocal. Soft
// sums combine in smem then one atomicAdd per point; last block finalizes.
// ---------------------------------------------------------------------------
__global__ __launch_bounds__(1024, 2) void k_all(const float* __restrict__ hm,
                                                 const float* __restrict__ pts,
                                                 float* __restrict__ out) {
    __shared__ float4 pre4[PP / 2];      // (-px0,-px1,dxs0,dxs1) quads
    __shared__ float  s_hm[WW];          // raw h for this row
    __shared__ float4 s_hb[WW / 2];      // (-h0,-h1,-bb0,-bb1) pixel-pair quads
    __shared__ float  s_min[4][256];     // per point-group min dist2
    __shared__ float  s_pb[PP];          // half-row soft partials
    __shared__ float  s_red[32], s_red2[32];
    __shared__ float  s_M;

    int tid = threadIdx.x;               // 0..1023
    int y   = blockIdx.x;                // row
    int tp  = tid & 511;                 // point index

    // ---- point table (quad layout, threads<512 write) + corner max ----------
    float py = pts[2 * tp], px = pts[2 * tp + 1];
    float dx = (float)y - py;
    if (tid < PP) {
        float* prefs = (float*)pre4;
        int cell = tp >> 1, par = tp & 1;
        prefs[cell * 4 + par]     = -px;
        prefs[cell * 4 + 2 + par] = dx * dx;
    }
    float my = fmaxf(py, 255.0f - py);
    float mx = fmaxf(px, 255.0f - px);
    float lmax = fmaf(my, my, mx * mx);  // separable -> corner attains max

    if (tid < WW) s_hm[tid] = hm[y * WW + tid];

    int warp = tid >> 5, lane = tid & 31;
    for (int o = 16; o > 0; o >>= 1)
        lmax = fmaxf(lmax, __shfl_down_sync(0xffffffffu, lmax, o));
    if (lane == 0) s_red[warp] = lmax;
    __syncthreads();
    if (tid == 0) {
        float m = s_red[0];
#pragma unroll
        for (int i = 1; i < 32; ++i) m = fmaxf(m, s_red[i]);
        s_M = sqrtf(m);
    }
    __syncthreads();
    float M = s_M;

    // ---- negated (h, bb) pixel-pair quads (threads < 128) -------------------
    if (tid < WW / 2) {
        float h0 = s_hm[2 * tid], h1 = s_hm[2 * tid + 1];
        s_hb[tid] = make_float4(-h0, -h1, fmaf(h0, M, -M), fmaf(h1, M, -M));
    }
    __syncthreads();

    // ---------------- Phase A: per-pixel min dist2 (4 threads/pixel) ---------
    {
        int p   = tid & 255;             // pixel
        int grp = tid >> 8;              // point group (0..3): 128 points each
        float xf = (float)p;
        ull XF2 = pk2(xf, xf);
        const float4* ptab = &pre4[grp * 64];
        float mins = 3.4e38f;
#pragma unroll 8
        for (int k = 0; k < 64; ++k) {
            float4 q = ptab[k];          // (-px0,-px1,dxs0,dxs1): aligned pairs
            ull NPX = pk2(q.x, q.y);
            ull DXS = pk2(q.z, q.w);
            ull DY  = f2add(XF2, NPX);
            ull S   = f2fma(DY, DY, DXS);
            float s0, s1; upk2(S, s0, s1);
            mins = fminf(mins, fminf(s0, s1));
        }
        s_min[grp][p] = mins;
    }
    __syncthreads();
    {
        float t1 = 0.f, ah = 0.f;
        if (tid < 256) {
            float mins = fminf(fminf(s_min[0][tid], s_min[1][tid]),
                               fminf(s_min[2][tid], s_min[3][tid]));
            float h = s_hm[tid];
            t1 = h * sqrtf(mins);
            ah = fabsf(h);
        }
        for (int o = 16; o > 0; o >>= 1) {
            t1 += __shfl_down_sync(0xffffffffu, t1, o);
            ah += __shfl_down_sync(0xffffffffu, ah, o);
        }
        if (tid < 256 && lane == 0) { s_red[warp] = t1; s_red2[warp] = ah; }
    }
    __syncthreads();
    if (tid == 0) {
        float a = 0.f, b = 0.f;
#pragma unroll
        for (int i = 0; i < 8; ++i) { a += s_red[i]; b += s_red2[i]; }
        g_numA[y] = a;
        g_denA[y] = b;
    }

    // ---------------- Phase B: half-row packed soft-min power sums -----------
    {
        int half = tid >> 9;             // which 128-pixel half
        const float* prefs = (const float*)pre4;
        int base = (tp >> 1) * 4 + (tp & 1);
        float np  = prefs[base];         // -px for point tp
        float dxs = prefs[base + 2];     // (y-py)^2
        float x0f = (float)(half * 128);

        ull DY   = pk2(np + x0f, np + x0f + 1.0f);
        ull DXS  = pk2(dxs, dxs);
        ull TWO2 = pk2(2.0f, 2.0f);
        ull ONE2 = pk2(1.0f, 1.0f);
        ull SACC = 0;
        const float4* hb = &s_hb[half * 64];

#pragma unroll 8
        for (int x = 0; x < 64; ++x) {
            float4 q = hb[x];                 // (-h0,-h1,-bb0,-bb1) one LDS.128
            ull NH2  = pk2(q.x, q.y);
            ull NBB2 = pk2(q.z, q.w);
            ull S    = f2fma(DY, DY, DXS);
            float sA, sB; upk2(S, sA, sB);
            float rA = frsqrt_a(sA);
            float rB = frsqrt_a(sB);
            ull R  = pk2(rA, rB);
            ull D  = f2mul(S, R);             // sqrt(s)
            ull NW = f2fma(NH2, D, NBB2);     // -w
            // packed Newton reciprocal from -w: seed = (magic|sign) - bits(-w)
            ull Y  = 0xFEF311C3FEF311C3ULL - NW;
            ull E;
            E = f2fma(NW, Y, ONE2); Y = f2fma(Y, E, Y);
            E = f2fma(NW, Y, ONE2); Y = f2fma(Y, E, Y);
            ull Q2 = f2mul(Y, Y);
            ull Q4 = f2mul(Q2, Q2);
            SACC = f2fma(Q4, Y, SACC);        // += w^-5
            DY = f2add(DY, TWO2);
        }
        float SA, SB; upk2(SACC, SA, SB);
        float Spart = SA + SB;
        if (half == 0) s_pb[tp] = Spart;
        __syncthreads();
        if (half == 1)
            atomicAdd(&g_sum[tp], s_pb[tp] + Spart);   // one atomic per point
    }

    // ---------------- last-block epilogue ------------------------------------
    __shared__ int s_last;
    __threadfence();
    __syncthreads();
    if (tid == 0) s_last = (atomicAdd(&g_ctr, 1) == (int)gridDim.x - 1);
    __syncthreads();
    if (!s_last) return;

    float* red = (float*)pre4;           // 1024 floats available
    float* r2  = (float*)s_hm;           // 256 floats
    float* r3  = (float*)s_min;          // 1024 floats
    if (tid < PP) {
        float Ssum = g_sum[tid];
        red[tid] = powf(Ssum * (1.0f / (HH * WW)), -0.2f);  // mean^(1/ALPHA)
        g_sum[tid] = 0.f;                // reset for next replay
    }
    if (tid < HH) { r2[tid] = g_numA[tid]; r3[tid] = g_denA[tid]; }
    __syncthreads();
    for (int o = 256; o > 0; o >>= 1) {
        if (tid < o) red[tid] += red[tid + o];
        __syncthreads();
    }
    for (int o = 128; o > 0; o >>= 1) {
        if (tid < o) { r2[tid] += r2[tid + o]; r3[tid] += r3[tid + o]; }
        __syncthreads();
    }
    if (tid == 0) {
        out[0] = r2[0] / r3[0] + red[0] * (1.0f / PP);
        g_ctr = 0;                       // reset for next replay
    }
}

extern "C" void kernel_launch(void* const* d_in, const int* in_sizes, int n_in,
                              void* d_out, int out_size) {
    (void)in_sizes; (void)n_in; (void)out_size;
    const float* hm  = (const float*)d_in[0];   // heat_map (256*256)
    const float* pts = (const float*)d_in[1];   // points   (512*2)
    float* out = (float*)d_out;

    k_all<<<HH, 1024>>>(hm, pts, out);
}

// round 10
// speedup vs baseline: 1.0820x; 1.0820x over previous
#include <cuda_runtime.h>

#define HH 256
#define WW 256
#define PP 512
// ALPHA = -5.0f, 1/ALPHA = -0.2f

typedef unsigned long long ull;

__device__ float g_sum[PP];          // zero-init at load; reset by epilogue
__device__ float g_numA[HH];
__device__ float g_denA[HH];
__device__ int   g_ctr = 0;

__device__ __forceinline__ float fsqrt_a(float x) {
    float r; asm("sqrt.approx.f32 %0, %1;" : "=f"(r) : "f"(x)); return r;
}
__device__ __forceinline__ float frcp_a(float x) {
    float r; asm("rcp.approx.f32 %0, %1;" : "=f"(r) : "f"(x)); return r;
}
__device__ __forceinline__ ull pk2(float lo, float hi) {
    ull r; asm("mov.b64 %0, {%1, %2};" : "=l"(r) : "f"(lo), "f"(hi)); return r;
}
__device__ __forceinline__ void upk2(ull v, float& lo, float& hi) {
    asm("mov.b64 {%0, %1}, %2;" : "=f"(lo), "=f"(hi) : "l"(v));
}
__device__ __forceinline__ ull f2add(ull a, ull b) {
    ull r; asm("add.rn.f32x2 %0, %1, %2;" : "=l"(r) : "l"(a), "l"(b)); return r;
}
__device__ __forceinline__ ull f2mul(ull a, ull b) {
    ull r; asm("mul.rn.f32x2 %0, %1, %2;" : "=l"(r) : "l"(a), "l"(b)); return r;
}
__device__ __forceinline__ ull f2fma(ull a, ull b, ull c) {
    ull r; asm("fma.rn.f32x2 %0, %1, %2, %3;" : "=l"(r) : "l"(a), "l"(b), "l"(c)); return r;
}

// ---------------------------------------------------------------------------
// Single fused kernel: 128 blocks x 1024 threads (one wave). Block b owns
// rows 2b, 2b+1. Phase B balances fma and MUFU pipes: sqrt.approx +
// rcp.approx (MUFU) carry the nonlinear work; f32x2 carries the rest.
// Soft sums via atomicAdd(g_sum); last block finalizes and resets state.
// ---------------------------------------------------------------------------
__global__ __launch_bounds__(1024, 1) void k_all(const float* __restrict__ hm,
                                                 const float* __restrict__ pts,
                                                 float* __restrict__ out) {
    __shared__ float4 pre4[2][PP / 2];   // per row: (-px0,-px1,dxs0,dxs1) quads
    __shared__ float  s_hm[2][WW];       // per row: raw h
    __shared__ float4 s_hb[2][WW / 2];   // per row: (h0,h1,bb0,bb1) quads
    __shared__ float  s_min[2][2][256];  // per row, per point-half: min dist2
    __shared__ float  s_red[32], s_red2[32];
    __shared__ float  s_M;

    int tid  = threadIdx.x;              // 0..1023
    int row  = tid >> 9;                 // 0/1 within the row pair
    int t    = tid & 511;                // point index within row
    int y    = blockIdx.x * 2 + row;

    // ---- per-row point table (quad layout) + corner max (separable) --------
    float py = pts[2 * t], px = pts[2 * t + 1];
    float dx = (float)y - py;
    {
        float* prefs = (float*)pre4[row];
        int cell = t >> 1, par = t & 1;
        prefs[cell * 4 + par]     = -px;
        prefs[cell * 4 + 2 + par] = dx * dx;
    }
    float my = fmaxf(py, 255.0f - py);
    float mx = fmaxf(px, 255.0f - px);
    float lmax = fmaf(my, my, mx * mx);

    float h = 0.f;
    if (t < WW) {
        h = hm[y * WW + t];
        s_hm[row][t] = h;
    }

    int warp = tid >> 5, lane = tid & 31;
    for (int o = 16; o > 0; o >>= 1)
        lmax = fmaxf(lmax, __shfl_down_sync(0xffffffffu, lmax, o));
    if (lane == 0) s_red[warp] = lmax;
    __syncthreads();
    if (tid == 0) {
        float m = s_red[0];
#pragma unroll
        for (int i = 1; i < 32; ++i) m = fmaxf(m, s_red[i]);
        s_M = sqrtf(m);
    }
    __syncthreads();
    float M = s_M;

    // ---- (h, bb) pixel-pair quads (t < 128 per row) -------------------------
    if (t < WW / 2) {
        float h0 = s_hm[row][2 * t], h1 = s_hm[row][2 * t + 1];
        s_hb[row][t] = make_float4(h0, h1, fmaf(-h0, M, M), fmaf(-h1, M, M));
    }
    __syncthreads();

    // ---------------- Phase A: per-pixel min dist2 (2 threads/pixel) --------
    {
        int p  = tid & 255;              // pixel
        int hp = (tid >> 8) & 1;         // which half of the points
        float xf = (float)p;
        ull XF2 = pk2(xf, xf);
        const float4* ptab = &pre4[row][hp * 128];
        float mins = 3.4e38f;
#pragma unroll 8
        for (int k = 0; k < 128; ++k) {
            float4 q = ptab[k];          // (-px0,-px1,dxs0,dxs1): aligned pairs
            ull NPX = pk2(q.x, q.y);
            ull DXS = pk2(q.z, q.w);
            ull DY  = f2add(XF2, NPX);
            ull S   = f2fma(DY, DY, DXS);
            float s0, s1; upk2(S, s0, s1);
            mins = fminf(mins, fminf(s0, s1));
        }
        s_min[row][hp][p] = mins;
    }
    __syncthreads();
    {
        int p  = tid & 255;
        int hp = (tid >> 8) & 1;
        float t1 = 0.f, ah = 0.f;
        if (hp == 0) {                   // these threads hold h for pixel p
            float mins = fminf(s_min[row][0][p], s_min[row][1][p]);
            t1 = h * sqrtf(mins);
            ah = fabsf(h);
        }
        for (int o = 16; o > 0; o >>= 1) {
            t1 += __shfl_down_sync(0xffffffffu, t1, o);
            ah += __shfl_down_sync(0xffffffffu, ah, o);
        }
        if (lane == 0) { s_red[warp] = t1; s_red2[warp] = ah; }
    }
    __syncthreads();
    if (t == 0) {                        // one finisher per row
        int w0 = row * 16;               // row's hp==0 warps
        float a = 0.f, b = 0.f;
#pragma unroll
        for (int i = 0; i < 8; ++i) { a += s_red[w0 + i]; b += s_red2[w0 + i]; }
        g_numA[y] = a;
        g_denA[y] = b;
    }

    // ---------------- Phase B: pixel-pair soft-min power sums (MUFU path) ----
    {
        const float* prefs = (const float*)pre4[row];
        int base = (t >> 1) * 4 + (t & 1);
        float np  = prefs[base];         // -px for point t
        float dxs = prefs[base + 2];     // (y-py)^2

        ull DY   = pk2(np, np + 1.0f);   // (x0-px, x1-px) at x=0
        ull DXS  = pk2(dxs, dxs);
        ull TWO2 = pk2(2.0f, 2.0f);
        ull SACC = 0;
        const float4* hb = s_hb[row];

#pragma unroll 8
        for (int x = 0; x < WW / 2; ++x) {
            float4 q = hb[x];                 // (h0,h1,bb0,bb1) one LDS.128
            ull H2  = pk2(q.x, q.y);
            ull BB2 = pk2(q.z, q.w);
            ull S   = f2fma(DY, DY, DXS);
            float sA, sB; upk2(S, sA, sB);
            float dA = fsqrt_a(sA);           // MUFU sqrt
            float dB = fsqrt_a(sB);
            ull D = pk2(dA, dB);
            ull W = f2fma(H2, D, BB2);        // w = h*d + (1-h)*M
            float wA, wB; upk2(W, wA, wB);
            float qA = frcp_a(wA);            // MUFU rcp
            float qB = frcp_a(wB);
            ull Y  = pk2(qA, qB);
            ull Q2 = f2mul(Y, Y);
            ull Q4 = f2mul(Q2, Q2);
            SACC = f2fma(Q4, Y, SACC);        // += w^-5
            DY = f2add(DY, TWO2);
        }
        float SA, SB; upk2(SACC, SA, SB);
        atomicAdd(&g_sum[t], SA + SB);        // one add per (row, point)
    }

    // ---------------- last-block epilogue ------------------------------------
    __shared__ int s_last;
    __threadfence();
    __syncthreads();
    if (tid == 0) s_last = (atomicAdd(&g_ctr, 1) == (int)gridDim.x - 1);
    __syncthreads();
    if (!s_last) return;

    float* red = (float*)pre4;           // reuse smem
    float* r2  = (float*)s_hm;
    float* r3  = (float*)s_min;
    if (tid < PP) {
        float Ssum = g_sum[tid];
        red[tid] = powf(Ssum * (1.0f / (HH * WW)), -0.2f);  // mean^(1/ALPHA)
        g_sum[tid] = 0.f;                // reset for next replay
    }
    if (tid < HH) { r2[tid] = g_numA[tid]; r3[tid] = g_denA[tid]; }
    __syncthreads();
    for (int o = 256; o > 0; o >>= 1) {
        if (tid < o) red[tid] += red[tid + o];
        __syncthreads();
    }
    for (int o = 128; o > 0; o >>= 1) {
        if (tid < o) { r2[tid] += r2[tid + o]; r3[tid] += r3[tid + o]; }
        __syncthreads();
    }
    if (tid == 0) {
        out[0] = r2[0] / r3[0] + red[0] * (1.0f / PP);
        g_ctr = 0;                       // reset for next replay
    }
}

extern "C" void kernel_launch(void* const* d_in, const int* in_sizes, int n_in,
                              void* d_out, int out_size) {
    (void)in_sizes; (void)n_in; (void)out_size;
    const float* hm  = (const float*)d_in[0];   // heat_map (256*256)
    const float* pts = (const float*)d_in[1];   // points   (512*2)
    float* out = (float*)d_out;

    k_all<<<HH / 2, 1024>>>(hm, pts, out);
}